// round 15
// baseline (speedup 1.0000x reference)
#include <cuda_runtime.h>
#include <cuda_fp16.h>
#include <math.h>
#include <stdint.h>

#define BB   8
#define NN   4096      // 64*64 tokens
#define CC   256
#define CIN  64
#define DHX  1024
#define MM   (BB*NN)   // 32768

// ---------------- scratch (device globals, no runtime alloc) ----------------
__device__ float  g_h   [MM*CC];
__device__ float  g_psi [MM*CC];
__device__ float  g_bufA[MM*CC];
__device__ float  g_bufB[MM*CC];
__device__ float  g_bufC[MM*CC];
__device__ float  g_U   [MM*CC];
__device__ float  g_kvT [BB*CC*CC];
__device__ float  g_ksum[BB*CC];
__device__ float  g_pool1[BB*CC];
__device__ float  g_pool2[BB*CC];
__device__ float  g_sgt [BB*CC];
__device__ float  g_psiT[9*CC];
__device__ float  g_dwT [9*DHX];
// fp16 buffers
__device__ __half g_h16   [MM*CC];
__device__ __half g_phiQ16[MM*CC];
__device__ __half g_numr16[MM*CC];
__device__ __half g_num16 [MM*CC];
__device__ __half g_attn16[MM*CC];
__device__ __half g_U16   [MM*CC];
__device__ __half g_U2_16 [MM*CC];
__device__ __half g_he16  [MM*DHX];
__device__ __half g_hg16  [MM*DHX];
__device__ __half g_kvT16 [BB*CC*CC];
__device__ __half g_wq16[CC*CC], g_wk16[CC*CC], g_wv16[CC*CC], g_wo16[CC*CC];
__device__ __half g_we16[DHX*CC], g_wp16[CC*DHX];

// ---------------- small device helpers ----------------
__device__ __forceinline__ float siluf(float x) { return x / (1.f + expf(-x)); }
__device__ __forceinline__ float sigm(float x)  { return 1.f / (1.f + expf(-x)); }
__device__ __forceinline__ float geluf(float x) {
    float x3 = x * x * x;
    return 0.5f * x * (1.f + tanhf(0.7978845608028654f * (x + 0.044715f * x3)));
}
__device__ __forceinline__ uint32_t tf32cvt(float f) {
    uint32_t u; asm("cvt.rna.tf32.f32 %0, %1;" : "=r"(u) : "f"(f)); return u;
}
__device__ __forceinline__ void mma_tf32(float* c, const uint32_t* a, const uint32_t* b) {
    asm volatile("mma.sync.aligned.m16n8k8.row.col.f32.tf32.tf32.f32 "
        "{%0,%1,%2,%3}, {%4,%5,%6,%7}, {%8,%9}, {%0,%1,%2,%3};"
        : "+f"(c[0]), "+f"(c[1]), "+f"(c[2]), "+f"(c[3])
        : "r"(a[0]), "r"(a[1]), "r"(a[2]), "r"(a[3]), "r"(b[0]), "r"(b[1]));
}
__device__ __forceinline__ void mma_f16(float* c, const uint32_t* a, const uint32_t* b) {
    asm volatile("mma.sync.aligned.m16n8k16.row.col.f32.f16.f16.f32 "
        "{%0,%1,%2,%3}, {%4,%5,%6,%7}, {%8,%9}, {%0,%1,%2,%3};"
        : "+f"(c[0]), "+f"(c[1]), "+f"(c[2]), "+f"(c[3])
        : "r"(a[0]), "r"(a[1]), "r"(a[2]), "r"(a[3]), "r"(b[0]), "r"(b[1]));
}
__device__ __forceinline__ void ldsm_x4(uint32_t& r0, uint32_t& r1, uint32_t& r2, uint32_t& r3,
                                        uint32_t saddr) {
    asm volatile("ldmatrix.sync.aligned.m8n8.x4.shared.b16 {%0,%1,%2,%3}, [%4];"
        : "=r"(r0), "=r"(r1), "=r"(r2), "=r"(r3) : "r"(saddr));
}

// ---------------- fused prep kernel: all weight converts + zeros ------------
#define PREP_TOTAL 1328384
__global__ void prep_kernel(
    const float* __restrict__ wq, const float* __restrict__ wk,
    const float* __restrict__ wv, const float* __restrict__ wo,
    const float* __restrict__ we, const float* __restrict__ wp,
    const float* __restrict__ psi_w, const float* __restrict__ dw_w,
    __half* __restrict__ wq16, __half* __restrict__ wk16,
    __half* __restrict__ wv16, __half* __restrict__ wo16,
    __half* __restrict__ we16, __half* __restrict__ wp16,
    float* __restrict__ psiT, float* __restrict__ dwT,
    float* __restrict__ kvT, float* __restrict__ ksum,
    float* __restrict__ pool1, float* __restrict__ pool2)
{
    int i = blockIdx.x * 256 + threadIdx.x;
    if (i < 65536)            wq16[i] = __float2half(wq[i]);
    else if (i < 131072)  { int j = i - 65536;  wk16[j] = __float2half(wk[j]); }
    else if (i < 196608)  { int j = i - 131072; wv16[j] = __float2half(wv[j]); }
    else if (i < 262144)  { int j = i - 196608; wo16[j] = __float2half(wo[j]); }
    else if (i < 524288)  { int j = i - 262144; we16[j] = __float2half(we[j]); }
    else if (i < 786432)  { int j = i - 524288; wp16[j] = __float2half(wp[j]); }
    else if (i < 788736)  { int j = i - 786432; int c = j / 9, t = j % 9; psiT[t * CC + c] = psi_w[j]; }
    else if (i < 797952)  { int j = i - 788736; int c = j / 9, t = j % 9; dwT[t * DHX + c] = dw_w[j]; }
    else if (i < 1322240) { kvT[i - 797952] = 0.f; }
    else if (i < 1324288) { ksum[i - 1322240] = 0.f; }
    else if (i < 1326336) { pool1[i - 1324288] = 0.f; }
    else if (i < 1328384) { pool2[i - 1326336] = 0.f; }
}

// ---------------- in_proj ----------------------------------------------------
__global__ __launch_bounds__(256) void in_proj_kernel(
    const float* __restrict__ x, const float* __restrict__ w,
    float* __restrict__ h, __half* __restrict__ h16)
{
    __shared__ float Xs[64][65];
    __shared__ float Ws[64][65];
    int b = blockIdx.z, n0 = blockIdx.x * 64, o0 = blockIdx.y * 64;
    int t = threadIdx.x;
#pragma unroll
    for (int i = 0; i < 4; i++) {
        int id = t + i * 256;
        int r  = id >> 4;
        int q  = (id & 15) * 4;
        float4 vx = *(const float4*)(x + ((long)b * CIN + r) * NN + n0 + q);
        Xs[r][q] = vx.x; Xs[r][q+1] = vx.y; Xs[r][q+2] = vx.z; Xs[r][q+3] = vx.w;
        float4 vw = *(const float4*)(w + (o0 + r) * CIN + q);
        Ws[q][r] = vw.x; Ws[q+1][r] = vw.y; Ws[q+2][r] = vw.z; Ws[q+3][r] = vw.w;
    }
    __syncthreads();
    int tx = t % 16, ty = t / 16;
    float acc[4][4] = {};
#pragma unroll
    for (int c = 0; c < 64; c++) {
        float fn[4], fo[4];
#pragma unroll
        for (int i = 0; i < 4; i++) fn[i] = Xs[c][ty*4 + i];
#pragma unroll
        for (int j = 0; j < 4; j++) fo[j] = Ws[c][tx*4 + j];
#pragma unroll
        for (int i = 0; i < 4; i++)
#pragma unroll
            for (int j = 0; j < 4; j++) acc[i][j] += fn[i] * fo[j];
    }
#pragma unroll
    for (int i = 0; i < 4; i++) {
        int n = n0 + ty*4 + i;
        float4 r;
        r.x = siluf(acc[i][0]); r.y = siluf(acc[i][1]);
        r.z = siluf(acc[i][2]); r.w = siluf(acc[i][3]);
        long off = ((long)b * NN + n) * CC + o0 + tx*4;
        *(float4*)(h + off) = r;
        uint2 hq;
        *(__half2*)&hq.x = __floats2half2_rn(r.x, r.y);
        *(__half2*)&hq.y = __floats2half2_rn(r.z, r.w);
        *(uint2*)(h16 + off) = hq;
    }
}

// ---------------- depthwise convs -------------------------------------------
__global__ void dwconv4_kernel(const float* __restrict__ in, const float* __restrict__ cwT,
                               const float* __restrict__ cb, float* __restrict__ outp)
{
    const int CG = CC / 4;
    long i = (long)blockIdx.x * 256 + threadIdx.x;
    int c4  = (int)(i % CG);
    long pix = i / CG;
    int hw  = (int)(pix & (NN - 1));
    int b   = (int)(pix >> 12);
    int hh  = hw >> 6, ww = hw & 63;
    int c = c4 * 4;
    float4 bias4 = *(const float4*)(cb + c);
    float ax = bias4.x, ay = bias4.y, az = bias4.z, aw = bias4.w;
    const float* base = in + ((long)b * NN) * CC + c;
#pragma unroll
    for (int ky = 0; ky < 3; ky++) {
        int hy = hh + ky - 1;
        if ((unsigned)hy >= 64u) continue;
#pragma unroll
        for (int kx = 0; kx < 3; kx++) {
            int wx = ww + kx - 1;
            if ((unsigned)wx >= 64u) continue;
            float4 v = *(const float4*)(base + (long)(hy * 64 + wx) * CC);
            float4 w = *(const float4*)(cwT + (ky * 3 + kx) * CC + c);
            ax += v.x * w.x; ay += v.y * w.y; az += v.z * w.z; aw += v.w * w.w;
        }
    }
    float4 r;
    r.x = sigm(ax); r.y = sigm(ay); r.z = sigm(az); r.w = sigm(aw);
    *(float4*)(outp + i * 4) = r;
}

__global__ void dwconv4h_kernel(const __half* __restrict__ in, const float* __restrict__ cwT,
                                const float* __restrict__ cb, __half* __restrict__ outp)
{
    const int CG = DHX / 4;
    long i = (long)blockIdx.x * 256 + threadIdx.x;
    int c4  = (int)(i % CG);
    long pix = i / CG;
    int hw  = (int)(pix & (NN - 1));
    int b   = (int)(pix >> 12);
    int hh  = hw >> 6, ww = hw & 63;
    int c = c4 * 4;
    float4 bias4 = *(const float4*)(cb + c);
    float ax = bias4.x, ay = bias4.y, az = bias4.z, aw = bias4.w;
    const __half* base = in + ((long)b * NN) * DHX + c;
#pragma unroll
    for (int ky = 0; ky < 3; ky++) {
        int hy = hh + ky - 1;
        if ((unsigned)hy >= 64u) continue;
#pragma unroll
        for (int kx = 0; kx < 3; kx++) {
            int wx = ww + kx - 1;
            if ((unsigned)wx >= 64u) continue;
            uint2 raw = *(const uint2*)(base + (long)(hy * 64 + wx) * DHX);
            float2 v0 = __half22float2(*(__half2*)&raw.x);
            float2 v1 = __half22float2(*(__half2*)&raw.y);
            float4 w = *(const float4*)(cwT + (ky * 3 + kx) * DHX + c);
            ax += v0.x * w.x; ay += v0.y * w.y; az += v1.x * w.z; aw += v1.y * w.w;
        }
    }
    uint2 o;
    *(__half2*)&o.x = __floats2half2_rn(geluf(ax), geluf(ay));
    *(__half2*)&o.y = __floats2half2_rn(geluf(az), geluf(aw));
    *(uint2*)(outp + i * 4) = o;
}

// ---------------- FP16 MMA GEMM, CTA 64x128, warp 32x32, 3 CTAs/SM, ldmatrix
// Out[M,N] = A[M,K] @ B[N,K]^T (+bias); MODE 1: + 2*aux(fp16). OUTH: half out.
template<int MODE, int OUTH>
__global__ __launch_bounds__(256, 3) void hgemm(
    const __half* __restrict__ A, const __half* __restrict__ B,
    const float* __restrict__ bias, const __half* __restrict__ aux,
    void* __restrict__ OutV, int Ndim, int Kdim,
    long aStrideB, long bStrideB, long oStrideB)
{
    __shared__ __half As[64][72];
    __shared__ __half Bs[128][72];
    int bz = blockIdx.z;
    A += (long)bz * aStrideB;
    B += (long)bz * bStrideB;
    float*  Outf = (float*)OutV  + (long)bz * oStrideB;
    __half* Outh = (__half*)OutV + (long)bz * oStrideB;
    int m0 = blockIdx.y * 64, n0 = blockIdx.x * 128;
    int tid = threadIdx.x, l = tid & 31, wid = tid >> 5;
    int wm = (wid >> 2) * 32, wn = (wid & 3) * 32;
    int lg = l >> 2, lt = l & 3;
    // ldmatrix lane mappings (validated in R10):
    int a_row = l & 15, a_koff = (l >> 4) * 8;
    int b_col = ((l >> 4) * 8) + (l & 7), b_koff = ((l >> 3) & 1) * 8;
    uint32_t smA = (uint32_t)__cvta_generic_to_shared(&As[0][0]);
    uint32_t smB = (uint32_t)__cvta_generic_to_shared(&Bs[0][0]);
    float acc[2][4][4] = {};
    for (int k0 = 0; k0 < Kdim; k0 += 64) {
#pragma unroll
        for (int i = 0; i < 2; i++) {
            int id = tid + i * 256;
            int r  = id >> 3;
            int cq = (id & 7) * 8;
            *(uint4*)&As[r][cq] = *(const uint4*)(A + (long)(m0 + r) * Kdim + k0 + cq);
        }
#pragma unroll
        for (int i = 0; i < 4; i++) {
            int id = tid + i * 256;
            int r  = id >> 3;
            int cq = (id & 7) * 8;
            *(uint4*)&Bs[r][cq] = *(const uint4*)(B + (long)(n0 + r) * Kdim + k0 + cq);
        }
        __syncthreads();
#pragma unroll
        for (int ks = 0; ks < 4; ks++) {
            int kk = ks * 16;
            uint32_t af[2][4], bf[4][2];
#pragma unroll
            for (int mi = 0; mi < 2; mi++) {
                uint32_t addr = smA + (uint32_t)(((wm + mi * 16 + a_row) * 72 + kk + a_koff) * 2);
                ldsm_x4(af[mi][0], af[mi][1], af[mi][2], af[mi][3], addr);
            }
#pragma unroll
            for (int pr = 0; pr < 2; pr++) {
                uint32_t addr = smB + (uint32_t)(((wn + pr * 16 + b_col) * 72 + kk + b_koff) * 2);
                ldsm_x4(bf[pr*2][0], bf[pr*2][1], bf[pr*2+1][0], bf[pr*2+1][1], addr);
            }
#pragma unroll
            for (int mi = 0; mi < 2; mi++)
#pragma unroll
                for (int ni = 0; ni < 4; ni++)
                    mma_f16(acc[mi][ni], af[mi], bf[ni]);
        }
        __syncthreads();
    }
#pragma unroll
    for (int mi = 0; mi < 2; mi++) {
        int r0 = m0 + wm + mi * 16 + lg;
        int r1 = r0 + 8;
#pragma unroll
        for (int ni = 0; ni < 4; ni++) {
            int c = n0 + wn + ni * 8 + lt * 2;
            float v0 = acc[mi][ni][0], v1 = acc[mi][ni][1];
            float v2 = acc[mi][ni][2], v3 = acc[mi][ni][3];
            if (bias) { v0 += bias[c]; v1 += bias[c+1]; v2 += bias[c]; v3 += bias[c+1]; }
            if (MODE == 1) {
                v0 += 2.f * __half2float(aux[(long)r0 * Ndim + c]);
                v1 += 2.f * __half2float(aux[(long)r0 * Ndim + c + 1]);
                v2 += 2.f * __half2float(aux[(long)r1 * Ndim + c]);
                v3 += 2.f * __half2float(aux[(long)r1 * Ndim + c + 1]);
            }
            if (OUTH) {
                *(__half2*)&Outh[(long)r0 * Ndim + c] = __floats2half2_rn(v0, v1);
                *(__half2*)&Outh[(long)r1 * Ndim + c] = __floats2half2_rn(v2, v3);
            } else {
                Outf[(long)r0 * Ndim + c]     = v0;
                Outf[(long)r0 * Ndim + c + 1] = v1;
                Outf[(long)r1 * Ndim + c]     = v2;
                Outf[(long)r1 * Ndim + c + 1] = v3;
            }
        }
    }
}

// ---------------- phi -------------------------------------------------------
__global__ void phi_kernel(const float* __restrict__ psi,
                           const float* __restrict__ qb, float* __restrict__ kb,
                           __half* __restrict__ phiQ16)
{
    int i = blockIdx.x * 256 + threadIdx.x;
    int c   = i & 255;
    int pix = i >> 8;
    int hw  = pix & (NN - 1);
    int hh  = hw >> 6, ww = hw & 63;
    int grp = c >> 6, ci = c & 63;
    float omega = expf(-(float)ci * (9.210340371976184f / 64.f));
    float coord = (grp < 2) ? (float)ww : (float)hh;
    float arg = coord * omega;
    float posv = ((grp & 1) == 0) ? sinf(arg) : cosf(arg);
    float ps = psi[i];
    float q = ps * (qb[i] + posv); q = fmaxf(q, 0.f); phiQ16[i] = __float2half(q * q);
    float k = ps * (kb[i] + posv); k = fmaxf(k, 0.f); kb[i] = k * k;
}

// ---------------- kvT TF32 mma ----------------------------------------------
__global__ __launch_bounds__(256) void kv_mma(
    const float* __restrict__ phiK, const float* __restrict__ V, float* __restrict__ kvT)
{
    __shared__ uint32_t Vs[32][132];
    __shared__ uint32_t Ks[32][132];
    int b = blockIdx.z >> 3, split = blockIdx.z & 7;
    int d0 = blockIdx.y * 128, c0 = blockIdx.x * 128;
    const float* Vp = V    + (long)b * NN * CC;
    const float* Kp = phiK + (long)b * NN * CC;
    int tid = threadIdx.x, wid = tid >> 5, l = tid & 31;
    int wm = (wid >> 2) * 64, wn = (wid & 3) * 32;
    int lg = l >> 2, lt = l & 3;
    float acc[4][4][4] = {};
    int nend = split * 512 + 512;
    for (int n0 = split * 512; n0 < nend; n0 += 32) {
#pragma unroll
        for (int i = 0; i < 4; i++) {
            int id = tid + i * 256;
            int nl = id >> 5;
            int q  = (id & 31) * 4;
            float4 v = *(const float4*)(Vp + (long)(n0 + nl) * CC + d0 + q);
            uint4 uv; uv.x = tf32cvt(v.x); uv.y = tf32cvt(v.y);
                      uv.z = tf32cvt(v.z); uv.w = tf32cvt(v.w);
            *(uint4*)&Vs[nl][q] = uv;
            float4 k = *(const float4*)(Kp + (long)(n0 + nl) * CC + c0 + q);
            uint4 uk; uk.x = tf32cvt(k.x); uk.y = tf32cvt(k.y);
                      uk.z = tf32cvt(k.z); uk.w = tf32cvt(k.w);
            *(uint4*)&Ks[nl][q] = uk;
        }
        __syncthreads();
#pragma unroll
        for (int ks = 0; ks < 4; ks++) {
            int kk = ks * 8;
            uint32_t af[4][4], bf[4][2];
#pragma unroll
            for (int mi = 0; mi < 4; mi++) {
                int rb = wm + mi * 16;
                af[mi][0] = Vs[kk + lt][rb + lg];
                af[mi][1] = Vs[kk + lt][rb + 8 + lg];
                af[mi][2] = Vs[kk + 4 + lt][rb + lg];
                af[mi][3] = Vs[kk + 4 + lt][rb + 8 + lg];
            }
#pragma unroll
            for (int ni = 0; ni < 4; ni++) {
                int cb = wn + ni * 8;
                bf[ni][0] = Ks[kk + lt][cb + lg];
                bf[ni][1] = Ks[kk + 4 + lt][cb + lg];
            }
#pragma unroll
            for (int mi = 0; mi < 4; mi++)
#pragma unroll
                for (int ni = 0; ni < 4; ni++)
                    mma_tf32(acc[mi][ni], af[mi], bf[ni]);
        }
        __syncthreads();
    }
    long base = (long)b * CC * CC;
#pragma unroll
    for (int mi = 0; mi < 4; mi++) {
        int r0 = d0 + wm + mi * 16 + lg;
        int r1 = r0 + 8;
#pragma unroll
        for (int ni = 0; ni < 4; ni++) {
            int c = c0 + wn + ni * 8 + lt * 2;
            atomicAdd(&kvT[base + (long)r0 * CC + c],     acc[mi][ni][0]);
            atomicAdd(&kvT[base + (long)r0 * CC + c + 1], acc[mi][ni][1]);
            atomicAdd(&kvT[base + (long)r1 * CC + c],     acc[mi][ni][2]);
            atomicAdd(&kvT[base + (long)r1 * CC + c + 1], acc[mi][ni][3]);
        }
    }
}

// ---------------- misc elementwise ------------------------------------------
__global__ void f2h_kernel(const float* __restrict__ in, __half* __restrict__ out, int n) {
    int i = blockIdx.x * 256 + threadIdx.x;
    if (i < n) out[i] = __float2half(in[i]);
}
__global__ void pool_kernel(const float* __restrict__ in, float* __restrict__ outp)
{
    int t = threadIdx.x;
    long base = (long)blockIdx.x * 256;
    int b = blockIdx.x >> 4;
    float acc = 0.f;
    for (int p = 0; p < 256; p++) acc += in[(base + p) * CC + t];
    atomicAdd(&outp[b * CC + t], acc);
}
__global__ void dendiv_kernel(const __half* __restrict__ phiQ16,
                              const float* __restrict__ ksum,
                              const __half* __restrict__ numr16, __half* __restrict__ num16)
{
    int warp = threadIdx.x >> 5, lane = threadIdx.x & 31;
    long pix = (long)blockIdx.x * 8 + warp;
    int b = (int)(pix >> 12);
    float s = 0.f;
#pragma unroll
    for (int k = 0; k < 8; k++) {
        int c = lane + k * 32;
        s += __half2float(phiQ16[pix * CC + c]) * ksum[b * CC + c];
    }
#pragma unroll
    for (int off = 16; off; off >>= 1) s += __shfl_xor_sync(0xffffffffu, s, off);
    float inv = 1.f / (s + 1e-5f);
#pragma unroll
    for (int k = 0; k < 8; k++) {
        int c = lane + k * 32;
        num16[pix * CC + c] = __float2half(__half2float(numr16[pix * CC + c]) * inv);
    }
}
__global__ void dyt_mix_kernel(const float* __restrict__ in1, const __half* __restrict__ in2h,
                               const float* __restrict__ gam, const float* __restrict__ bet,
                               float* __restrict__ outp)
{
    int warp = threadIdx.x >> 5, lane = threadIdx.x & 31;
    long pix = (long)blockIdx.x * 8 + warp;
    float v[8];
    float s = 0.f, sq = 0.f;
#pragma unroll
    for (int k = 0; k < 8; k++) {
        int c = lane + k * 32;
        float x = in1[pix * CC + c];
        if (in2h) x += __half2float(in2h[pix * CC + c]);
        v[k] = x; s += x; sq += x * x;
    }
#pragma unroll
    for (int off = 16; off; off >>= 1) {
        s  += __shfl_xor_sync(0xffffffffu, s,  off);
        sq += __shfl_xor_sync(0xffffffffu, sq, off);
    }
    float mu  = s * (1.f / 256.f);
    float var = fmaxf(sq - 256.f * mu * mu, 0.f) * (1.f / 255.f);
    float sd  = sqrtf(var) + 1e-5f;
    float inv = 1.f / sd;
#pragma unroll
    for (int k = 0; k < 8; k++) {
        int c = lane + k * 32;
        outp[pix * CC + c] = tanhf(gam[c] * (v[k] - mu) * inv + bet[c]);
    }
}
__global__ void dyt_h_kernel(const __half* __restrict__ in1,
                             const float* __restrict__ gam, const float* __restrict__ bet,
                             float* __restrict__ outp)
{
    int warp = threadIdx.x >> 5, lane = threadIdx.x & 31;
    long pix = (long)blockIdx.x * 8 + warp;
    float v[8];
    float s = 0.f, sq = 0.f;
#pragma unroll
    for (int k = 0; k < 8; k++) {
        int c = lane + k * 32;
        float x = __half2float(in1[pix * CC + c]);
        v[k] = x; s += x; sq += x * x;
    }
#pragma unroll
    for (int off = 16; off; off >>= 1) {
        s  += __shfl_xor_sync(0xffffffffu, s,  off);
        sq += __shfl_xor_sync(0xffffffffu, sq, off);
    }
    float mu  = s * (1.f / 256.f);
    float var = fmaxf(sq - 256.f * mu * mu, 0.f) * (1.f / 255.f);
    float sd  = sqrtf(var) + 1e-5f;
    float inv = 1.f / sd;
#pragma unroll
    for (int k = 0; k < 8; k++) {
        int c = lane + k * 32;
        outp[pix * CC + c] = tanhf(gam[c] * (v[k] - mu) * inv + bet[c]);
    }
}
__global__ void monafc_kernel(const float* __restrict__ pool,
                              const float* __restrict__ mw, const float* __restrict__ mb,
                              float* __restrict__ sgate)
{
    int b = blockIdx.x, o = threadIdx.x;
    float acc = mb[o];
    const float invN = 1.f / (float)NN;
    for (int c = 0; c < CC; c++)
        acc += pool[b * CC + c] * invN * mw[o * CC + c];
    sgate[b * CC + o] = sigm(acc);
}
__global__ void gate_kernel(float* __restrict__ p, const float* __restrict__ sgate,
                            __half* __restrict__ out16)
{
    long i = (long)blockIdx.x * 256 + threadIdx.x;
    int c = (int)(i & 255);
    long pix = i >> 8;
    int b = (int)(pix >> 12);
    float v = p[i] * sgate[b * CC + c];
    p[i] = v;
    if (out16) out16[i] = __float2half(v);
}

// ---------------- out_proj ---------------------------------------------------
__global__ __launch_bounds__(256) void out_proj_kernel(
    const __half* __restrict__ Y, const float* __restrict__ w, float* __restrict__ outp)
{
    __shared__ float Ys[64][65];
    __shared__ float Ws[64][65];
    int b = blockIdx.z, n0 = blockIdx.x * 64;
    int t = threadIdx.x;
    int tx = t % 16, ty = t / 16;
    float acc[4][4] = {};
    for (int ck = 0; ck < CC; ck += 64) {
#pragma unroll
        for (int i = 0; i < 4; i++) {
            int id = t + i * 256;
            int r  = id >> 4;
            int cq = (id & 15) * 4;
            uint2 raw = *(const uint2*)(Y + ((long)b * NN + n0 + r) * CC + ck + cq);
            float2 f0 = __half22float2(*(__half2*)&raw.x);
            float2 f1 = __half22float2(*(__half2*)&raw.y);
            Ys[cq][r] = f0.x; Ys[cq+1][r] = f0.y; Ys[cq+2][r] = f1.x; Ys[cq+3][r] = f1.y;
            float4 vw = *(const float4*)(w + r * CC + ck + cq);
            Ws[cq][r] = vw.x; Ws[cq+1][r] = vw.y; Ws[cq+2][r] = vw.z; Ws[cq+3][r] = vw.w;
        }
        __syncthreads();
#pragma unroll
        for (int c = 0; c < 64; c++) {
            float fn[4], fo[4];
#pragma unroll
            for (int i = 0; i < 4; i++) fn[i] = Ys[c][tx*4 + i];
#pragma unroll
            for (int j = 0; j < 4; j++) fo[j] = Ws[c][ty*4 + j];
#pragma unroll
            for (int j = 0; j < 4; j++)
#pragma unroll
                for (int i = 0; i < 4; i++) acc[j][i] += fo[j] * fn[i];
        }
        __syncthreads();
    }
#pragma unroll
    for (int j = 0; j < 4; j++) {
        int o = ty*4 + j;
        float4 r;
        r.x = siluf(acc[j][0]); r.y = siluf(acc[j][1]);
        r.z = siluf(acc[j][2]); r.w = siluf(acc[j][3]);
        *(float4*)(outp + ((long)b * 64 + o) * NN + n0 + tx*4) = r;
    }
}

// ---------------- launch ----------------------------------------------------
extern "C" void kernel_launch(void* const* d_in, const int* in_sizes, int n_in,
                              void* d_out, int out_size)
{
    const float* x         = (const float*)d_in[0];
    const float* in_proj_w = (const float*)d_in[1];
    const float* wq_w = (const float*)d_in[2];  const float* wq_b = (const float*)d_in[3];
    const float* wk_w = (const float*)d_in[4];  const float* wk_b = (const float*)d_in[5];
    const float* wv_w = (const float*)d_in[6];  const float* wv_b = (const float*)d_in[7];
    const float* wo_w = (const float*)d_in[8];  const float* wo_b = (const float*)d_in[9];
    const float* psi_w = (const float*)d_in[10]; const float* psi_b = (const float*)d_in[11];
    const float* dyt_g = (const float*)d_in[12]; const float* dyt_b = (const float*)d_in[13];
    const float* m1_w = (const float*)d_in[14]; const float* m1_b = (const float*)d_in[15];
    const float* m2_w = (const float*)d_in[16]; const float* m2_b = (const float*)d_in[17];
    const float* we_w = (const float*)d_in[18]; const float* we_b = (const float*)d_in[19];
    const float* dw_w = (const float*)d_in[20]; const float* dw_b = (const float*)d_in[21];
    const float* wp_w = (const float*)d_in[22]; const float* wp_b = (const float*)d_in[23];
    const float* out_proj_w = (const float*)d_in[24];
    float* outp = (float*)d_out;

    float *p_h, *p_psi, *p_A, *p_B, *p_C, *p_U;
    float *p_kvT, *p_ksum, *p_pool1, *p_pool2, *p_s, *p_psiT, *p_dwT;
    __half *p_h16, *p_phiQ16, *p_numr16, *p_num16, *p_attn16, *p_U16, *p_U2;
    __half *p_he16, *p_hg16, *p_kvT16;
    __half *p_wq16, *p_wk16, *p_wv16, *p_wo16, *p_we16, *p_wp16;
    cudaGetSymbolAddress((void**)&p_h,    g_h);
    cudaGetSymbolAddress((void**)&p_psi,  g_psi);
    cudaGetSymbolAddress((void**)&p_A,    g_bufA);
    cudaGetSymbolAddress((void**)&p_B,    g_bufB);
    cudaGetSymbolAddress((void**)&p_C,    g_bufC);
    cudaGetSymbolAddress((void**)&p_U,    g_U);
    cudaGetSymbolAddress((void**)&p_kvT,  g_kvT);
    cudaGetSymbolAddress((void**)&p_ksum, g_ksum);
    cudaGetSymbolAddress((void**)&p_pool1, g_pool1);
    cudaGetSymbolAddress((void**)&p_pool2, g_pool2);
    cudaGetSymbolAddress((void**)&p_s,    g_sgt);
    cudaGetSymbolAddress((void**)&p_psiT, g_psiT);
    cudaGetSymbolAddress((void**)&p_dwT,  g_dwT);
    cudaGetSymbolAddress((void**)&p_h16,    g_h16);
    cudaGetSymbolAddress((void**)&p_phiQ16, g_phiQ16);
    cudaGetSymbolAddress((void**)&p_numr16, g_numr16);
    cudaGetSymbolAddress((void**)&p_num16,  g_num16);
    cudaGetSymbolAddress((void**)&p_attn16, g_attn16);
    cudaGetSymbolAddress((void**)&p_U16,    g_U16);
    cudaGetSymbolAddress((void**)&p_U2,     g_U2_16);
    cudaGetSymbolAddress((void**)&p_he16,   g_he16);
    cudaGetSymbolAddress((void**)&p_hg16,   g_hg16);
    cudaGetSymbolAddress((void**)&p_kvT16,  g_kvT16);
    cudaGetSymbolAddress((void**)&p_wq16, g_wq16);
    cudaGetSymbolAddress((void**)&p_wk16, g_wk16);
    cudaGetSymbolAddress((void**)&p_wv16, g_wv16);
    cudaGetSymbolAddress((void**)&p_wo16, g_wo16);
    cudaGetSymbolAddress((void**)&p_we16, g_we16);
    cudaGetSymbolAddress((void**)&p_wp16, g_wp16);

    // single fused prep launch
    prep_kernel<<<(PREP_TOTAL + 255) / 256, 256>>>(
        wq_w, wk_w, wv_w, wo_w, we_w, wp_w, psi_w, dw_w,
        p_wq16, p_wk16, p_wv16, p_wo16, p_we16, p_wp16,
        p_psiT, p_dwT, p_kvT, p_ksum, p_pool1, p_pool2);

    // 1) in_proj + SiLU
    in_proj_kernel<<<dim3(NN/64, CC/64, BB), 256>>>(x, in_proj_w, p_h, p_h16);

    // 2) psi
    dwconv4_kernel<<<MM*(CC/4)/256, 256>>>(p_h, p_psiT, psi_b, p_psi);

    // 3) Q/K/V projections
    hgemm<0,0><<<dim3(CC/128, MM/64, 1), 256>>>(p_h16, p_wq16, wq_b, nullptr, p_A, CC, CC, 0, 0, 0);
    hgemm<0,0><<<dim3(CC/128, MM/64, 1), 256>>>(p_h16, p_wk16, wk_b, nullptr, p_B, CC, CC, 0, 0, 0);
    hgemm<0,0><<<dim3(CC/128, MM/64, 1), 256>>>(p_h16, p_wv16, wv_b, nullptr, p_C, CC, CC, 0, 0, 0);

    // 4) phi
    phi_kernel<<<MM*CC/256, 256>>>(p_psi, p_A, p_B, p_phiQ16);

    // 5) ksum
    pool_kernel<<<BB*16, 256>>>(p_B, p_ksum);

    // 6) kvT + fp16 copy
    kv_mma<<<dim3(CC/128, CC/128, BB*8), 256>>>(p_B, p_C, p_kvT);
    f2h_kernel<<<(BB*CC*CC + 255) / 256, 256>>>(p_kvT, p_kvT16, BB*CC*CC);

    // 7) numr16 = phiQ @ kvT^T (batched, fp16 out)
    hgemm<0,1><<<dim3(CC/128, NN/64, BB), 256>>>(
        p_phiQ16, p_kvT16, nullptr, nullptr, p_numr16, CC, CC,
        (long)NN*CC, (long)CC*CC, (long)NN*CC);

    // 8) dendiv
    dendiv_kernel<<<MM/8, 256>>>(p_phiQ16, p_ksum, p_numr16, p_num16);

    // 9) attn16 = num @ wo^T + b
    hgemm<0,1><<<dim3(CC/128, MM/64, 1), 256>>>(
        p_num16, p_wo16, wo_b, nullptr, p_attn16, CC, CC, 0, 0, 0);

    // 10) DyT 1
    dyt_mix_kernel<<<MM/8, 256>>>(p_h, p_attn16, dyt_g, dyt_b, p_U);

    // 11) Mona 1
    pool_kernel<<<BB*16, 256>>>(p_U, p_pool1);
    monafc_kernel<<<BB, 256>>>(p_pool1, m1_w, m1_b, p_s);
    gate_kernel<<<MM*CC/256, 256>>>(p_U, p_s, p_U16);

    // 12) EDFFN
    hgemm<0,1><<<dim3(DHX/128, MM/64, 1), 256>>>(
        p_U16, p_we16, we_b, nullptr, p_he16, DHX, CC, 0, 0, 0);
    dwconv4h_kernel<<<MM*(DHX/4)/256, 256>>>(p_he16, p_dwT, dw_b, p_hg16);
    hgemm<1,1><<<dim3(CC/128, MM/64, 1), 256>>>(
        p_hg16, p_wp16, wp_b, p_U16, p_U2, CC, DHX, 0, 0, 0);

    // 13) DyT 2 + Mona 2
    dyt_h_kernel<<<MM/8, 256>>>(p_U2, dyt_g, dyt_b, p_U);
    pool_kernel<<<BB*16, 256>>>(p_U, p_pool2);
    monafc_kernel<<<BB, 256>>>(p_pool2, m2_w, m2_b, p_s);
    gate_kernel<<<MM*CC/256, 256>>>(p_U, p_s, p_U16);

    // 14) out_proj + SiLU
    out_proj_kernel<<<dim3(NN/64, 1, BB), 256>>>(p_U16, out_proj_w, outp);
}

// round 16
// speedup vs baseline: 1.4972x; 1.4972x over previous
#include <cuda_runtime.h>
#include <cuda_fp16.h>
#include <math.h>
#include <stdint.h>

#define BB   8
#define NN   4096      // 64*64 tokens
#define CC   256
#define CIN  64
#define DHX  1024
#define MM   (BB*NN)   // 32768

// ---------------- scratch (device globals, no runtime alloc) ----------------
__device__ float  g_h   [MM*CC];
__device__ float  g_psi [MM*CC];
__device__ float  g_bufA[MM*CC];
__device__ float  g_bufB[MM*CC];
__device__ float  g_bufC[MM*CC];
__device__ float  g_U   [MM*CC];
__device__ float  g_kvT [BB*CC*CC];
__device__ float  g_ksum[BB*CC];
__device__ float  g_pool1[BB*CC];
__device__ float  g_pool2[BB*CC];
__device__ float  g_sgt [BB*CC];
__device__ float  g_psiT[9*CC];
__device__ float  g_dwT [9*DHX];
// fp16 buffers
__device__ __half g_h16   [MM*CC];
__device__ __half g_phiQ16[MM*CC];
__device__ __half g_numr16[MM*CC];
__device__ __half g_num16 [MM*CC];
__device__ __half g_attn16[MM*CC];
__device__ __half g_U16   [MM*CC];
__device__ __half g_U2_16 [MM*CC];
__device__ __half g_he16  [MM*DHX];
__device__ __half g_hg16  [MM*DHX];
__device__ __half g_kvT16 [BB*CC*CC];
__device__ __half g_wq16[CC*CC], g_wk16[CC*CC], g_wv16[CC*CC], g_wo16[CC*CC];
__device__ __half g_we16[DHX*CC], g_wp16[CC*DHX];

// ---------------- small device helpers ----------------
__device__ __forceinline__ float siluf(float x) { return x / (1.f + expf(-x)); }
__device__ __forceinline__ float sigm(float x)  { return 1.f / (1.f + expf(-x)); }
__device__ __forceinline__ float geluf(float x) {
    float x3 = x * x * x;
    return 0.5f * x * (1.f + tanhf(0.7978845608028654f * (x + 0.044715f * x3)));
}
__device__ __forceinline__ uint32_t tf32cvt(float f) {
    uint32_t u; asm("cvt.rna.tf32.f32 %0, %1;" : "=r"(u) : "f"(f)); return u;
}
__device__ __forceinline__ void mma_tf32(float* c, const uint32_t* a, const uint32_t* b) {
    asm volatile("mma.sync.aligned.m16n8k8.row.col.f32.tf32.tf32.f32 "
        "{%0,%1,%2,%3}, {%4,%5,%6,%7}, {%8,%9}, {%0,%1,%2,%3};"
        : "+f"(c[0]), "+f"(c[1]), "+f"(c[2]), "+f"(c[3])
        : "r"(a[0]), "r"(a[1]), "r"(a[2]), "r"(a[3]), "r"(b[0]), "r"(b[1]));
}
__device__ __forceinline__ void mma_f16(float* c, const uint32_t* a, const uint32_t* b) {
    asm volatile("mma.sync.aligned.m16n8k16.row.col.f32.f16.f16.f32 "
        "{%0,%1,%2,%3}, {%4,%5,%6,%7}, {%8,%9}, {%0,%1,%2,%3};"
        : "+f"(c[0]), "+f"(c[1]), "+f"(c[2]), "+f"(c[3])
        : "r"(a[0]), "r"(a[1]), "r"(a[2]), "r"(a[3]), "r"(b[0]), "r"(b[1]));
}
__device__ __forceinline__ void cpa16(void* s, const void* g) {
    uint32_t sa = (uint32_t)__cvta_generic_to_shared(s);
    asm volatile("cp.async.cg.shared.global [%0], [%1], 16;" :: "r"(sa), "l"(g));
}
__device__ __forceinline__ void cpa_commit() { asm volatile("cp.async.commit_group;"); }
template<int N> __device__ __forceinline__ void cpa_wait() {
    asm volatile("cp.async.wait_group %0;" :: "n"(N));
}

// ---------------- fused prep kernel: all weight converts + zeros ------------
#define PREP_TOTAL 1328384
__global__ void prep_kernel(
    const float* __restrict__ wq, const float* __restrict__ wk,
    const float* __restrict__ wv, const float* __restrict__ wo,
    const float* __restrict__ we, const float* __restrict__ wp,
    const float* __restrict__ psi_w, const float* __restrict__ dw_w,
    __half* __restrict__ wq16, __half* __restrict__ wk16,
    __half* __restrict__ wv16, __half* __restrict__ wo16,
    __half* __restrict__ we16, __half* __restrict__ wp16,
    float* __restrict__ psiT, float* __restrict__ dwT,
    float* __restrict__ kvT, float* __restrict__ ksum,
    float* __restrict__ pool1, float* __restrict__ pool2)
{
    int i = blockIdx.x * 256 + threadIdx.x;
    if (i < 65536)            wq16[i] = __float2half(wq[i]);
    else if (i < 131072)  { int j = i - 65536;  wk16[j] = __float2half(wk[j]); }
    else if (i < 196608)  { int j = i - 131072; wv16[j] = __float2half(wv[j]); }
    else if (i < 262144)  { int j = i - 196608; wo16[j] = __float2half(wo[j]); }
    else if (i < 524288)  { int j = i - 262144; we16[j] = __float2half(we[j]); }
    else if (i < 786432)  { int j = i - 524288; wp16[j] = __float2half(wp[j]); }
    else if (i < 788736)  { int j = i - 786432; int c = j / 9, t = j % 9; psiT[t * CC + c] = psi_w[j]; }
    else if (i < 797952)  { int j = i - 788736; int c = j / 9, t = j % 9; dwT[t * DHX + c] = dw_w[j]; }
    else if (i < 1322240) { kvT[i - 797952] = 0.f; }
    else if (i < 1324288) { ksum[i - 1322240] = 0.f; }
    else if (i < 1326336) { pool1[i - 1324288] = 0.f; }
    else if (i < 1328384) { pool2[i - 1326336] = 0.f; }
}

// ---------------- in_proj ----------------------------------------------------
__global__ __launch_bounds__(256) void in_proj_kernel(
    const float* __restrict__ x, const float* __restrict__ w,
    float* __restrict__ h, __half* __restrict__ h16)
{
    __shared__ float Xs[64][65];
    __shared__ float Ws[64][65];
    int b = blockIdx.z, n0 = blockIdx.x * 64, o0 = blockIdx.y * 64;
    int t = threadIdx.x;
#pragma unroll
    for (int i = 0; i < 4; i++) {
        int id = t + i * 256;
        int r  = id >> 4;
        int q  = (id & 15) * 4;
        float4 vx = *(const float4*)(x + ((long)b * CIN + r) * NN + n0 + q);
        Xs[r][q] = vx.x; Xs[r][q+1] = vx.y; Xs[r][q+2] = vx.z; Xs[r][q+3] = vx.w;
        float4 vw = *(const float4*)(w + (o0 + r) * CIN + q);
        Ws[q][r] = vw.x; Ws[q+1][r] = vw.y; Ws[q+2][r] = vw.z; Ws[q+3][r] = vw.w;
    }
    __syncthreads();
    int tx = t % 16, ty = t / 16;
    float acc[4][4] = {};
#pragma unroll
    for (int c = 0; c < 64; c++) {
        float fn[4], fo[4];
#pragma unroll
        for (int i = 0; i < 4; i++) fn[i] = Xs[c][ty*4 + i];
#pragma unroll
        for (int j = 0; j < 4; j++) fo[j] = Ws[c][tx*4 + j];
#pragma unroll
        for (int i = 0; i < 4; i++)
#pragma unroll
            for (int j = 0; j < 4; j++) acc[i][j] += fn[i] * fo[j];
    }
#pragma unroll
    for (int i = 0; i < 4; i++) {
        int n = n0 + ty*4 + i;
        float4 r;
        r.x = siluf(acc[i][0]); r.y = siluf(acc[i][1]);
        r.z = siluf(acc[i][2]); r.w = siluf(acc[i][3]);
        long off = ((long)b * NN + n) * CC + o0 + tx*4;
        *(float4*)(h + off) = r;
        uint2 hq;
        *(__half2*)&hq.x = __floats2half2_rn(r.x, r.y);
        *(__half2*)&hq.y = __floats2half2_rn(r.z, r.w);
        *(uint2*)(h16 + off) = hq;
    }
}

// ---------------- depthwise convs -------------------------------------------
__global__ void dwconv4_kernel(const float* __restrict__ in, const float* __restrict__ cwT,
                               const float* __restrict__ cb, float* __restrict__ outp)
{
    const int CG = CC / 4;
    long i = (long)blockIdx.x * 256 + threadIdx.x;
    int c4  = (int)(i % CG);
    long pix = i / CG;
    int hw  = (int)(pix & (NN - 1));
    int b   = (int)(pix >> 12);
    int hh  = hw >> 6, ww = hw & 63;
    int c = c4 * 4;
    float4 bias4 = *(const float4*)(cb + c);
    float ax = bias4.x, ay = bias4.y, az = bias4.z, aw = bias4.w;
    const float* base = in + ((long)b * NN) * CC + c;
#pragma unroll
    for (int ky = 0; ky < 3; ky++) {
        int hy = hh + ky - 1;
        if ((unsigned)hy >= 64u) continue;
#pragma unroll
        for (int kx = 0; kx < 3; kx++) {
            int wx = ww + kx - 1;
            if ((unsigned)wx >= 64u) continue;
            float4 v = *(const float4*)(base + (long)(hy * 64 + wx) * CC);
            float4 w = *(const float4*)(cwT + (ky * 3 + kx) * CC + c);
            ax += v.x * w.x; ay += v.y * w.y; az += v.z * w.z; aw += v.w * w.w;
        }
    }
    float4 r;
    r.x = sigm(ax); r.y = sigm(ay); r.z = sigm(az); r.w = sigm(aw);
    *(float4*)(outp + i * 4) = r;
}

__global__ void dwconv4h_kernel(const __half* __restrict__ in, const float* __restrict__ cwT,
                                const float* __restrict__ cb, __half* __restrict__ outp)
{
    const int CG = DHX / 4;
    long i = (long)blockIdx.x * 256 + threadIdx.x;
    int c4  = (int)(i % CG);
    long pix = i / CG;
    int hw  = (int)(pix & (NN - 1));
    int b   = (int)(pix >> 12);
    int hh  = hw >> 6, ww = hw & 63;
    int c = c4 * 4;
    float4 bias4 = *(const float4*)(cb + c);
    float ax = bias4.x, ay = bias4.y, az = bias4.z, aw = bias4.w;
    const __half* base = in + ((long)b * NN) * DHX + c;
#pragma unroll
    for (int ky = 0; ky < 3; ky++) {
        int hy = hh + ky - 1;
        if ((unsigned)hy >= 64u) continue;
#pragma unroll
        for (int kx = 0; kx < 3; kx++) {
            int wx = ww + kx - 1;
            if ((unsigned)wx >= 64u) continue;
            uint2 raw = *(const uint2*)(base + (long)(hy * 64 + wx) * DHX);
            float2 v0 = __half22float2(*(__half2*)&raw.x);
            float2 v1 = __half22float2(*(__half2*)&raw.y);
            float4 w = *(const float4*)(cwT + (ky * 3 + kx) * DHX + c);
            ax += v0.x * w.x; ay += v0.y * w.y; az += v1.x * w.z; aw += v1.y * w.w;
        }
    }
    uint2 o;
    *(__half2*)&o.x = __floats2half2_rn(geluf(ax), geluf(ay));
    *(__half2*)&o.y = __floats2half2_rn(geluf(az), geluf(aw));
    *(uint2*)(outp + i * 4) = o;
}

// ---------------- FP16 MMA GEMM: CTA 64x128, warp 32x32, 3 CTAs/SM,
// k-tile 32 double-buffered cp.async, scalar LDS fragments -------------------
// Out[M,N] = A[M,K] @ B[N,K]^T (+bias); MODE 1: + 2*aux(fp16). OUTH: half out.
template<int MODE, int OUTH>
__global__ __launch_bounds__(256, 3) void hgemm(
    const __half* __restrict__ A, const __half* __restrict__ B,
    const float* __restrict__ bias, const __half* __restrict__ aux,
    void* __restrict__ OutV, int Ndim, int Kdim,
    long aStrideB, long bStrideB, long oStrideB)
{
    __shared__ __half As[2][64][40];
    __shared__ __half Bs[2][128][40];
    int bz = blockIdx.z;
    A += (long)bz * aStrideB;
    B += (long)bz * bStrideB;
    float*  Outf = (float*)OutV  + (long)bz * oStrideB;
    __half* Outh = (__half*)OutV + (long)bz * oStrideB;
    int m0 = blockIdx.y * 64, n0 = blockIdx.x * 128;
    int tid = threadIdx.x, l = tid & 31, wid = tid >> 5;
    int wm = (wid >> 2) * 32, wn = (wid & 3) * 32;
    int lg = l >> 2, lt = l & 3;
    // staging lanes: A tile 64x32 -> 256 chunks of 16B (1/thread);
    //                B tile 128x32 -> 512 chunks (2/thread)
    int ra = tid >> 2,  ca = (tid & 3) * 8;     // A row, half-offset
    const __half* Ap = A + (long)(m0 + ra) * Kdim + ca;
    int rb0 = tid >> 2, cb0 = (tid & 3) * 8;    // B rows pass 0 (rows 0-63)
    const __half* Bp0 = B + (long)(n0 + rb0) * Kdim + cb0;
    const __half* Bp1 = B + (long)(n0 + 64 + rb0) * Kdim + cb0;
    int nt = Kdim >> 5;
    // preload buf 0
    cpa16(&As[0][ra][ca], Ap);
    cpa16(&Bs[0][rb0][cb0], Bp0);
    cpa16(&Bs[0][64 + rb0][cb0], Bp1);
    cpa_commit();
    float acc[2][4][4] = {};
    for (int kt = 0; kt < nt; kt++) {
        int buf = kt & 1;
        if (kt + 1 < nt) {
            int ko = (kt + 1) * 32;
            int nb = buf ^ 1;
            cpa16(&As[nb][ra][ca], Ap + ko);
            cpa16(&Bs[nb][rb0][cb0], Bp0 + ko);
            cpa16(&Bs[nb][64 + rb0][cb0], Bp1 + ko);
            cpa_commit();
            cpa_wait<1>();
        } else {
            cpa_wait<0>();
        }
        __syncthreads();
#pragma unroll
        for (int ks = 0; ks < 2; ks++) {
            int kk = ks * 16;
            uint32_t af[2][4], bf[4][2];
#pragma unroll
            for (int mi = 0; mi < 2; mi++) {
                int rbr = wm + mi * 16 + lg;
                af[mi][0] = *(const uint32_t*)&As[buf][rbr][kk + 2*lt];
                af[mi][1] = *(const uint32_t*)&As[buf][rbr + 8][kk + 2*lt];
                af[mi][2] = *(const uint32_t*)&As[buf][rbr][kk + 8 + 2*lt];
                af[mi][3] = *(const uint32_t*)&As[buf][rbr + 8][kk + 8 + 2*lt];
            }
#pragma unroll
            for (int ni = 0; ni < 4; ni++) {
                int cbr = wn + ni * 8 + lg;
                bf[ni][0] = *(const uint32_t*)&Bs[buf][cbr][kk + 2*lt];
                bf[ni][1] = *(const uint32_t*)&Bs[buf][cbr][kk + 8 + 2*lt];
            }
#pragma unroll
            for (int mi = 0; mi < 2; mi++)
#pragma unroll
                for (int ni = 0; ni < 4; ni++)
                    mma_f16(acc[mi][ni], af[mi], bf[ni]);
        }
        __syncthreads();
    }
#pragma unroll
    for (int mi = 0; mi < 2; mi++) {
        int r0 = m0 + wm + mi * 16 + lg;
        int r1 = r0 + 8;
#pragma unroll
        for (int ni = 0; ni < 4; ni++) {
            int c = n0 + wn + ni * 8 + lt * 2;
            float v0 = acc[mi][ni][0], v1 = acc[mi][ni][1];
            float v2 = acc[mi][ni][2], v3 = acc[mi][ni][3];
            if (bias) { v0 += bias[c]; v1 += bias[c+1]; v2 += bias[c]; v3 += bias[c+1]; }
            if (MODE == 1) {
                v0 += 2.f * __half2float(aux[(long)r0 * Ndim + c]);
                v1 += 2.f * __half2float(aux[(long)r0 * Ndim + c + 1]);
                v2 += 2.f * __half2float(aux[(long)r1 * Ndim + c]);
                v3 += 2.f * __half2float(aux[(long)r1 * Ndim + c + 1]);
            }
            if (OUTH) {
                *(__half2*)&Outh[(long)r0 * Ndim + c] = __floats2half2_rn(v0, v1);
                *(__half2*)&Outh[(long)r1 * Ndim + c] = __floats2half2_rn(v2, v3);
            } else {
                Outf[(long)r0 * Ndim + c]     = v0;
                Outf[(long)r0 * Ndim + c + 1] = v1;
                Outf[(long)r1 * Ndim + c]     = v2;
                Outf[(long)r1 * Ndim + c + 1] = v3;
            }
        }
    }
}

// ---------------- phi -------------------------------------------------------
__global__ void phi_kernel(const float* __restrict__ psi,
                           const float* __restrict__ qb, float* __restrict__ kb,
                           __half* __restrict__ phiQ16)
{
    int i = blockIdx.x * 256 + threadIdx.x;
    int c   = i & 255;
    int pix = i >> 8;
    int hw  = pix & (NN - 1);
    int hh  = hw >> 6, ww = hw & 63;
    int grp = c >> 6, ci = c & 63;
    float omega = expf(-(float)ci * (9.210340371976184f / 64.f));
    float coord = (grp < 2) ? (float)ww : (float)hh;
    float arg = coord * omega;
    float posv = ((grp & 1) == 0) ? sinf(arg) : cosf(arg);
    float ps = psi[i];
    float q = ps * (qb[i] + posv); q = fmaxf(q, 0.f); phiQ16[i] = __float2half(q * q);
    float k = ps * (kb[i] + posv); k = fmaxf(k, 0.f); kb[i] = k * k;
}

// ---------------- kvT TF32 mma ----------------------------------------------
__global__ __launch_bounds__(256) void kv_mma(
    const float* __restrict__ phiK, const float* __restrict__ V, float* __restrict__ kvT)
{
    __shared__ uint32_t Vs[32][132];
    __shared__ uint32_t Ks[32][132];
    int b = blockIdx.z >> 3, split = blockIdx.z & 7;
    int d0 = blockIdx.y * 128, c0 = blockIdx.x * 128;
    const float* Vp = V    + (long)b * NN * CC;
    const float* Kp = phiK + (long)b * NN * CC;
    int tid = threadIdx.x, wid = tid >> 5, l = tid & 31;
    int wm = (wid >> 2) * 64, wn = (wid & 3) * 32;
    int lg = l >> 2, lt = l & 3;
    float acc[4][4][4] = {};
    int nend = split * 512 + 512;
    for (int n0 = split * 512; n0 < nend; n0 += 32) {
#pragma unroll
        for (int i = 0; i < 4; i++) {
            int id = tid + i * 256;
            int nl = id >> 5;
            int q  = (id & 31) * 4;
            float4 v = *(const float4*)(Vp + (long)(n0 + nl) * CC + d0 + q);
            uint4 uv; uv.x = tf32cvt(v.x); uv.y = tf32cvt(v.y);
                      uv.z = tf32cvt(v.z); uv.w = tf32cvt(v.w);
            *(uint4*)&Vs[nl][q] = uv;
            float4 k = *(const float4*)(Kp + (long)(n0 + nl) * CC + c0 + q);
            uint4 uk; uk.x = tf32cvt(k.x); uk.y = tf32cvt(k.y);
                      uk.z = tf32cvt(k.z); uk.w = tf32cvt(k.w);
            *(uint4*)&Ks[nl][q] = uk;
        }
        __syncthreads();
#pragma unroll
        for (int ks = 0; ks < 4; ks++) {
            int kk = ks * 8;
            uint32_t af[4][4], bf[4][2];
#pragma unroll
            for (int mi = 0; mi < 4; mi++) {
                int rb = wm + mi * 16;
                af[mi][0] = Vs[kk + lt][rb + lg];
                af[mi][1] = Vs[kk + lt][rb + 8 + lg];
                af[mi][2] = Vs[kk + 4 + lt][rb + lg];
                af[mi][3] = Vs[kk + 4 + lt][rb + 8 + lg];
            }
#pragma unroll
            for (int ni = 0; ni < 4; ni++) {
                int cb = wn + ni * 8;
                bf[ni][0] = Ks[kk + lt][cb + lg];
                bf[ni][1] = Ks[kk + 4 + lt][cb + lg];
            }
#pragma unroll
            for (int mi = 0; mi < 4; mi++)
#pragma unroll
                for (int ni = 0; ni < 4; ni++)
                    mma_tf32(acc[mi][ni], af[mi], bf[ni]);
        }
        __syncthreads();
    }
    long base = (long)b * CC * CC;
#pragma unroll
    for (int mi = 0; mi < 4; mi++) {
        int r0 = d0 + wm + mi * 16 + lg;
        int r1 = r0 + 8;
#pragma unroll
        for (int ni = 0; ni < 4; ni++) {
            int c = c0 + wn + ni * 8 + lt * 2;
            atomicAdd(&kvT[base + (long)r0 * CC + c],     acc[mi][ni][0]);
            atomicAdd(&kvT[base + (long)r0 * CC + c + 1], acc[mi][ni][1]);
            atomicAdd(&kvT[base + (long)r1 * CC + c],     acc[mi][ni][2]);
            atomicAdd(&kvT[base + (long)r1 * CC + c + 1], acc[mi][ni][3]);
        }
    }
}

// ---------------- misc elementwise ------------------------------------------
__global__ void f2h_kernel(const float* __restrict__ in, __half* __restrict__ out, int n) {
    int i = blockIdx.x * 256 + threadIdx.x;
    if (i < n) out[i] = __float2half(in[i]);
}
__global__ void pool_kernel(const float* __restrict__ in, float* __restrict__ outp)
{
    int t = threadIdx.x;
    long base = (long)blockIdx.x * 256;
    int b = blockIdx.x >> 4;
    float acc = 0.f;
    for (int p = 0; p < 256; p++) acc += in[(base + p) * CC + t];
    atomicAdd(&outp[b * CC + t], acc);
}
__global__ void dendiv_kernel(const __half* __restrict__ phiQ16,
                              const float* __restrict__ ksum,
                              const __half* __restrict__ numr16, __half* __restrict__ num16)
{
    int warp = threadIdx.x >> 5, lane = threadIdx.x & 31;
    long pix = (long)blockIdx.x * 8 + warp;
    int b = (int)(pix >> 12);
    float s = 0.f;
#pragma unroll
    for (int k = 0; k < 8; k++) {
        int c = lane + k * 32;
        s += __half2float(phiQ16[pix * CC + c]) * ksum[b * CC + c];
    }
#pragma unroll
    for (int off = 16; off; off >>= 1) s += __shfl_xor_sync(0xffffffffu, s, off);
    float inv = 1.f / (s + 1e-5f);
#pragma unroll
    for (int k = 0; k < 8; k++) {
        int c = lane + k * 32;
        num16[pix * CC + c] = __float2half(__half2float(numr16[pix * CC + c]) * inv);
    }
}
__global__ void dyt_mix_kernel(const float* __restrict__ in1, const __half* __restrict__ in2h,
                               const float* __restrict__ gam, const float* __restrict__ bet,
                               float* __restrict__ outp)
{
    int warp = threadIdx.x >> 5, lane = threadIdx.x & 31;
    long pix = (long)blockIdx.x * 8 + warp;
    float v[8];
    float s = 0.f, sq = 0.f;
#pragma unroll
    for (int k = 0; k < 8; k++) {
        int c = lane + k * 32;
        float x = in1[pix * CC + c];
        if (in2h) x += __half2float(in2h[pix * CC + c]);
        v[k] = x; s += x; sq += x * x;
    }
#pragma unroll
    for (int off = 16; off; off >>= 1) {
        s  += __shfl_xor_sync(0xffffffffu, s,  off);
        sq += __shfl_xor_sync(0xffffffffu, sq, off);
    }
    float mu  = s * (1.f / 256.f);
    float var = fmaxf(sq - 256.f * mu * mu, 0.f) * (1.f / 255.f);
    float sd  = sqrtf(var) + 1e-5f;
    float inv = 1.f / sd;
#pragma unroll
    for (int k = 0; k < 8; k++) {
        int c = lane + k * 32;
        outp[pix * CC + c] = tanhf(gam[c] * (v[k] - mu) * inv + bet[c]);
    }
}
__global__ void dyt_h_kernel(const __half* __restrict__ in1,
                             const float* __restrict__ gam, const float* __restrict__ bet,
                             float* __restrict__ outp)
{
    int warp = threadIdx.x >> 5, lane = threadIdx.x & 31;
    long pix = (long)blockIdx.x * 8 + warp;
    float v[8];
    float s = 0.f, sq = 0.f;
#pragma unroll
    for (int k = 0; k < 8; k++) {
        int c = lane + k * 32;
        float x = __half2float(in1[pix * CC + c]);
        v[k] = x; s += x; sq += x * x;
    }
#pragma unroll
    for (int off = 16; off; off >>= 1) {
        s  += __shfl_xor_sync(0xffffffffu, s,  off);
        sq += __shfl_xor_sync(0xffffffffu, sq, off);
    }
    float mu  = s * (1.f / 256.f);
    float var = fmaxf(sq - 256.f * mu * mu, 0.f) * (1.f / 255.f);
    float sd  = sqrtf(var) + 1e-5f;
    float inv = 1.f / sd;
#pragma unroll
    for (int k = 0; k < 8; k++) {
        int c = lane + k * 32;
        outp[pix * CC + c] = tanhf(gam[c] * (v[k] - mu) * inv + bet[c]);
    }
}
__global__ void monafc_kernel(const float* __restrict__ pool,
                              const float* __restrict__ mw, const float* __restrict__ mb,
                              float* __restrict__ sgate)
{
    int b = blockIdx.x, o = threadIdx.x;
    float acc = mb[o];
    const float invN = 1.f / (float)NN;
    for (int c = 0; c < CC; c++)
        acc += pool[b * CC + c] * invN * mw[o * CC + c];
    sgate[b * CC + o] = sigm(acc);
}
__global__ void gate_kernel(float* __restrict__ p, const float* __restrict__ sgate,
                            __half* __restrict__ out16)
{
    long i = (long)blockIdx.x * 256 + threadIdx.x;
    int c = (int)(i & 255);
    long pix = i >> 8;
    int b = (int)(pix >> 12);
    float v = p[i] * sgate[b * CC + c];
    p[i] = v;
    if (out16) out16[i] = __float2half(v);
}

// ---------------- out_proj ---------------------------------------------------
__global__ __launch_bounds__(256) void out_proj_kernel(
    const __half* __restrict__ Y, const float* __restrict__ w, float* __restrict__ outp)
{
    __shared__ float Ys[64][65];
    __shared__ float Ws[64][65];
    int b = blockIdx.z, n0 = blockIdx.x * 64;
    int t = threadIdx.x;
    int tx = t % 16, ty = t / 16;
    float acc[4][4] = {};
    for (int ck = 0; ck < CC; ck += 64) {
#pragma unroll
        for (int i = 0; i < 4; i++) {
            int id = t + i * 256;
            int r  = id >> 4;
            int cq = (id & 15) * 4;
            uint2 raw = *(const uint2*)(Y + ((long)b * NN + n0 + r) * CC + ck + cq);
            float2 f0 = __half22float2(*(__half2*)&raw.x);
            float2 f1 = __half22float2(*(__half2*)&raw.y);
            Ys[cq][r] = f0.x; Ys[cq+1][r] = f0.y; Ys[cq+2][r] = f1.x; Ys[cq+3][r] = f1.y;
            float4 vw = *(const float4*)(w + r * CC + ck + cq);
            Ws[cq][r] = vw.x; Ws[cq+1][r] = vw.y; Ws[cq+2][r] = vw.z; Ws[cq+3][r] = vw.w;
        }
        __syncthreads();
#pragma unroll
        for (int c = 0; c < 64; c++) {
            float fn[4], fo[4];
#pragma unroll
            for (int i = 0; i < 4; i++) fn[i] = Ys[c][tx*4 + i];
#pragma unroll
            for (int j = 0; j < 4; j++) fo[j] = Ws[c][ty*4 + j];
#pragma unroll
            for (int j = 0; j < 4; j++)
#pragma unroll
                for (int i = 0; i < 4; i++) acc[j][i] += fo[j] * fn[i];
        }
        __syncthreads();
    }
#pragma unroll
    for (int j = 0; j < 4; j++) {
        int o = ty*4 + j;
        float4 r;
        r.x = siluf(acc[j][0]); r.y = siluf(acc[j][1]);
        r.z = siluf(acc[j][2]); r.w = siluf(acc[j][3]);
        *(float4*)(outp + ((long)b * 64 + o) * NN + n0 + tx*4) = r;
    }
}

// ---------------- launch ----------------------------------------------------
extern "C" void kernel_launch(void* const* d_in, const int* in_sizes, int n_in,
                              void* d_out, int out_size)
{
    const float* x         = (const float*)d_in[0];
    const float* in_proj_w = (const float*)d_in[1];
    const float* wq_w = (const float*)d_in[2];  const float* wq_b = (const float*)d_in[3];
    const float* wk_w = (const float*)d_in[4];  const float* wk_b = (const float*)d_in[5];
    const float* wv_w = (const float*)d_in[6];  const float* wv_b = (const float*)d_in[7];
    const float* wo_w = (const float*)d_in[8];  const float* wo_b = (const float*)d_in[9];
    const float* psi_w = (const float*)d_in[10]; const float* psi_b = (const float*)d_in[11];
    const float* dyt_g = (const float*)d_in[12]; const float* dyt_b = (const float*)d_in[13];
    const float* m1_w = (const float*)d_in[14]; const float* m1_b = (const float*)d_in[15];
    const float* m2_w = (const float*)d_in[16]; const float* m2_b = (const float*)d_in[17];
    const float* we_w = (const float*)d_in[18]; const float* we_b = (const float*)d_in[19];
    const float* dw_w = (const float*)d_in[20]; const float* dw_b = (const float*)d_in[21];
    const float* wp_w = (const float*)d_in[22]; const float* wp_b = (const float*)d_in[23];
    const float* out_proj_w = (const float*)d_in[24];
    float* outp = (float*)d_out;

    float *p_h, *p_psi, *p_A, *p_B, *p_C, *p_U;
    float *p_kvT, *p_ksum, *p_pool1, *p_pool2, *p_s, *p_psiT, *p_dwT;
    __half *p_h16, *p_phiQ16, *p_numr16, *p_num16, *p_attn16, *p_U16, *p_U2;
    __half *p_he16, *p_hg16, *p_kvT16;
    __half *p_wq16, *p_wk16, *p_wv16, *p_wo16, *p_we16, *p_wp16;
    cudaGetSymbolAddress((void**)&p_h,    g_h);
    cudaGetSymbolAddress((void**)&p_psi,  g_psi);
    cudaGetSymbolAddress((void**)&p_A,    g_bufA);
    cudaGetSymbolAddress((void**)&p_B,    g_bufB);
    cudaGetSymbolAddress((void**)&p_C,    g_bufC);
    cudaGetSymbolAddress((void**)&p_U,    g_U);
    cudaGetSymbolAddress((void**)&p_kvT,  g_kvT);
    cudaGetSymbolAddress((void**)&p_ksum, g_ksum);
    cudaGetSymbolAddress((void**)&p_pool1, g_pool1);
    cudaGetSymbolAddress((void**)&p_pool2, g_pool2);
    cudaGetSymbolAddress((void**)&p_s,    g_sgt);
    cudaGetSymbolAddress((void**)&p_psiT, g_psiT);
    cudaGetSymbolAddress((void**)&p_dwT,  g_dwT);
    cudaGetSymbolAddress((void**)&p_h16,    g_h16);
    cudaGetSymbolAddress((void**)&p_phiQ16, g_phiQ16);
    cudaGetSymbolAddress((void**)&p_numr16, g_numr16);
    cudaGetSymbolAddress((void**)&p_num16,  g_num16);
    cudaGetSymbolAddress((void**)&p_attn16, g_attn16);
    cudaGetSymbolAddress((void**)&p_U16,    g_U16);
    cudaGetSymbolAddress((void**)&p_U2,     g_U2_16);
    cudaGetSymbolAddress((void**)&p_he16,   g_he16);
    cudaGetSymbolAddress((void**)&p_hg16,   g_hg16);
    cudaGetSymbolAddress((void**)&p_kvT16,  g_kvT16);
    cudaGetSymbolAddress((void**)&p_wq16, g_wq16);
    cudaGetSymbolAddress((void**)&p_wk16, g_wk16);
    cudaGetSymbolAddress((void**)&p_wv16, g_wv16);
    cudaGetSymbolAddress((void**)&p_wo16, g_wo16);
    cudaGetSymbolAddress((void**)&p_we16, g_we16);
    cudaGetSymbolAddress((void**)&p_wp16, g_wp16);

    // single fused prep launch
    prep_kernel<<<(PREP_TOTAL + 255) / 256, 256>>>(
        wq_w, wk_w, wv_w, wo_w, we_w, wp_w, psi_w, dw_w,
        p_wq16, p_wk16, p_wv16, p_wo16, p_we16, p_wp16,
        p_psiT, p_dwT, p_kvT, p_ksum, p_pool1, p_pool2);

    // 1) in_proj + SiLU
    in_proj_kernel<<<dim3(NN/64, CC/64, BB), 256>>>(x, in_proj_w, p_h, p_h16);

    // 2) psi
    dwconv4_kernel<<<MM*(CC/4)/256, 256>>>(p_h, p_psiT, psi_b, p_psi);

    // 3) Q/K/V projections
    hgemm<0,0><<<dim3(CC/128, MM/64, 1), 256>>>(p_h16, p_wq16, wq_b, nullptr, p_A, CC, CC, 0, 0, 0);
    hgemm<0,0><<<dim3(CC/128, MM/64, 1), 256>>>(p_h16, p_wk16, wk_b, nullptr, p_B, CC, CC, 0, 0, 0);
    hgemm<0,0><<<dim3(CC/128, MM/64, 1), 256>>>(p_h16, p_wv16, wv_b, nullptr, p_C, CC, CC, 0, 0, 0);

    // 4) phi
    phi_kernel<<<MM*CC/256, 256>>>(p_psi, p_A, p_B, p_phiQ16);

    // 5) ksum
    pool_kernel<<<BB*16, 256>>>(p_B, p_ksum);

    // 6) kvT + fp16 copy
    kv_mma<<<dim3(CC/128, CC/128, BB*8), 256>>>(p_B, p_C, p_kvT);
    f2h_kernel<<<(BB*CC*CC + 255) / 256, 256>>>(p_kvT, p_kvT16, BB*CC*CC);

    // 7) numr16 = phiQ @ kvT^T (batched, fp16 out)
    hgemm<0,1><<<dim3(CC/128, NN/64, BB), 256>>>(
        p_phiQ16, p_kvT16, nullptr, nullptr, p_numr16, CC, CC,
        (long)NN*CC, (long)CC*CC, (long)NN*CC);

    // 8) dendiv
    dendiv_kernel<<<MM/8, 256>>>(p_phiQ16, p_ksum, p_numr16, p_num16);

    // 9) attn16 = num @ wo^T + b
    hgemm<0,1><<<dim3(CC/128, MM/64, 1), 256>>>(
        p_num16, p_wo16, wo_b, nullptr, p_attn16, CC, CC, 0, 0, 0);

    // 10) DyT 1
    dyt_mix_kernel<<<MM/8, 256>>>(p_h, p_attn16, dyt_g, dyt_b, p_U);

    // 11) Mona 1
    pool_kernel<<<BB*16, 256>>>(p_U, p_pool1);
    monafc_kernel<<<BB, 256>>>(p_pool1, m1_w, m1_b, p_s);
    gate_kernel<<<MM*CC/256, 256>>>(p_U, p_s, p_U16);

    // 12) EDFFN
    hgemm<0,1><<<dim3(DHX/128, MM/64, 1), 256>>>(
        p_U16, p_we16, we_b, nullptr, p_he16, DHX, CC, 0, 0, 0);
    dwconv4h_kernel<<<MM*(DHX/4)/256, 256>>>(p_he16, p_dwT, dw_b, p_hg16);
    hgemm<1,1><<<dim3(CC/128, MM/64, 1), 256>>>(
        p_hg16, p_wp16, wp_b, p_U16, p_U2, CC, DHX, 0, 0, 0);

    // 13) DyT 2 + Mona 2
    dyt_h_kernel<<<MM/8, 256>>>(p_U2, dyt_g, dyt_b, p_U);
    pool_kernel<<<BB*16, 256>>>(p_U, p_pool2);
    monafc_kernel<<<BB, 256>>>(p_pool2, m2_w, m2_b, p_s);
    gate_kernel<<<MM*CC/256, 256>>>(p_U, p_s, p_U16);

    // 14) out_proj + SiLU
    out_proj_kernel<<<dim3(NN/64, 1, BB), 256>>>(p_U16, out_proj_w, outp);
}